// round 7
// baseline (speedup 1.0000x reference)
#include <cuda_runtime.h>
#include <cstdint>

#define BB 64
#define TT 1024
#define II 64
#define HH 512
#define GG 1536
#define MM (BB*TT)

typedef unsigned long long u64;

__device__ float g_xg[(size_t)MM * GG];
__device__ float g_y [(size_t)MM * HH];
__device__ float g_h [2][BB * HH];
__device__ unsigned g_bar4[4];

__device__ __forceinline__ void ffma2(u64 &d, u64 a, u64 b) {
    asm("fma.rn.f32x2 %0,%1,%2,%0;" : "+l"(d) : "l"(a), "l"(b));
}
__device__ __forceinline__ u64 pack2(float x, float y) {
    u64 r; asm("mov.b64 %0,{%1,%2};" : "=l"(r) : "f"(x), "f"(y)); return r;
}
__device__ __forceinline__ float2 unpack2(u64 v) {
    float2 f; asm("mov.b64 {%0,%1},%2;" : "=f"(f.x), "=f"(f.y) : "l"(v)); return f;
}
__device__ __forceinline__ u64 add2(u64 a, u64 b) {
    asm("add.rn.f32x2 %0,%0,%1;" : "+l"(a) : "l"(b)); return a;
}

__global__ void k_zero() {
    int i = blockIdx.x * blockDim.x + threadIdx.x;
    if (i < 4) g_bar4[i] = 0u;
    float* p = &g_h[0][0];
    for (int idx = i; idx < 2 * BB * HH; idx += gridDim.x * blockDim.x) p[idx] = 0.f;
}

// C[M,N] = A[M,K] @ W[N,K]^T + bias. FFMA2 inner, double-buffered smem.
template <int BM, int BN, int BK, int TM, int TNP>
__global__ __launch_bounds__(256, 2)
void sgemm_bias(const float* __restrict__ A, const float* __restrict__ W,
                const float* __restrict__ bias, float* __restrict__ C,
                int M, int N, int K)
{
    __shared__ u64   As2[2][BK][BM];
    __shared__ float Ws [2][BK][BN];
    constexpr int NA = BM * BK / 4 / 256;
    constexpr int NW = BN * BK / 4 / 256;
    const int tid = threadIdx.x, c = tid & 15, r = tid >> 4;
    const int m0 = blockIdx.y * BM, n0 = blockIdx.x * BN;

    u64 acc[TM][TNP];
#pragma unroll
    for (int i = 0; i < TM; i++)
#pragma unroll
        for (int j = 0; j < TNP; j++) acc[i][j] = 0ull;

#pragma unroll
    for (int q = 0; q < NA; q++) {
        int i = tid + q * 256;
        int am = i / (BK / 4), ak = (i % (BK / 4)) * 4;
        float4 v = *(const float4*)(A + (size_t)(m0 + am) * K + ak);
        As2[0][ak][am] = pack2(v.x, v.x); As2[0][ak + 1][am] = pack2(v.y, v.y);
        As2[0][ak + 2][am] = pack2(v.z, v.z); As2[0][ak + 3][am] = pack2(v.w, v.w);
    }
#pragma unroll
    for (int q = 0; q < NW; q++) {
        int i = tid + q * 256;
        int wn = i / (BK / 4), wk = (i % (BK / 4)) * 4;
        float4 v = *(const float4*)(W + (size_t)(n0 + wn) * K + wk);
        Ws[0][wk][wn] = v.x; Ws[0][wk + 1][wn] = v.y;
        Ws[0][wk + 2][wn] = v.z; Ws[0][wk + 3][wn] = v.w;
    }
    __syncthreads();

    int buf = 0;
    for (int k0 = 0; k0 < K; k0 += BK) {
        const int kn = k0 + BK;
        float4 pa[NA], pw[NW];
        if (kn < K) {
#pragma unroll
            for (int q = 0; q < NA; q++) {
                int i = tid + q * 256;
                int am = i / (BK / 4), ak = (i % (BK / 4)) * 4;
                pa[q] = *(const float4*)(A + (size_t)(m0 + am) * K + kn + ak);
            }
#pragma unroll
            for (int q = 0; q < NW; q++) {
                int i = tid + q * 256;
                int wn = i / (BK / 4), wk = (i % (BK / 4)) * 4;
                pw[q] = *(const float4*)(W + (size_t)(n0 + wn) * K + kn + wk);
            }
        }
#pragma unroll
        for (int kk = 0; kk < BK; kk++) {
            u64 a2[TM], b2[TNP];
#pragma unroll
            for (int i = 0; i < TM; i++) a2[i] = As2[buf][kk][r + 16 * i];
#pragma unroll
            for (int j = 0; j < TNP; j++) b2[j] = *(const u64*)&Ws[buf][kk][2 * c + 32 * j];
#pragma unroll
            for (int i = 0; i < TM; i++)
#pragma unroll
                for (int j = 0; j < TNP; j++) ffma2(acc[i][j], a2[i], b2[j]);
        }
        if (kn < K) {
            int nb = buf ^ 1;
#pragma unroll
            for (int q = 0; q < NA; q++) {
                int i = tid + q * 256;
                int am = i / (BK / 4), ak = (i % (BK / 4)) * 4;
                As2[nb][ak][am] = pack2(pa[q].x, pa[q].x);
                As2[nb][ak + 1][am] = pack2(pa[q].y, pa[q].y);
                As2[nb][ak + 2][am] = pack2(pa[q].z, pa[q].z);
                As2[nb][ak + 3][am] = pack2(pa[q].w, pa[q].w);
            }
#pragma unroll
            for (int q = 0; q < NW; q++) {
                int i = tid + q * 256;
                int wn = i / (BK / 4), wk = (i % (BK / 4)) * 4;
                Ws[nb][wk][wn] = pw[q].x; Ws[nb][wk + 1][wn] = pw[q].y;
                Ws[nb][wk + 2][wn] = pw[q].z; Ws[nb][wk + 3][wn] = pw[q].w;
            }
        }
        __syncthreads();
        buf ^= 1;
    }
#pragma unroll
    for (int i = 0; i < TM; i++) {
        int m = m0 + r + 16 * i;
#pragma unroll
        for (int j = 0; j < TNP; j++) {
            int col = n0 + 2 * c + 32 * j;
            u64 res = add2(acc[i][j], *(const u64*)(bias + col));
            *(u64*)(C + (size_t)m * N + col) = res;
        }
    }
}

// Persistent GRU scan: 128 CTAs (4 bg x 32 hs) x 512 thr.
// warp = 4 jl x 8 ks (4-way LDS.128 broadcast). Thread (jl, ks): 16-float k-slice.
// Reduction: 3-round in-warp reduce-scatter over 8 ks-lanes, then smem combine
// over 4 cross-warp ks-groups by 256 finisher threads.
__global__ __launch_bounds__(512, 1)
void gru_scan(const float* __restrict__ w_hh, const float* __restrict__ b_hh)
{
    __shared__ float4 hs4[32 * 65];    // slice ks: 65 float4-units (16 b x 4 + pad)
    __shared__ float  Rsm[4 * 817];    // [kshi][gate*272 + b*17 + jl]
    const int tid  = threadIdx.x;
    const int lane = tid & 31, wrp = tid >> 5;
    const int hsid = blockIdx.x & 31, bg = blockIdx.x >> 5;
    const int jl   = (wrp & 3) * 4 + (lane >> 3);
    const int ks   = ((wrp >> 2) & 3) * 8 + (lane & 7);
    const int kshi = (wrp >> 2) & 3;
    const int ksin = lane & 7;
    const int jhid = hsid * 16 + jl;

    u64 w2r[24];
#pragma unroll
    for (int g = 0; g < 3; g++) {
        const u64* wp = (const u64*)(w_hh + (size_t)(g * HH + jhid) * HH + ks * 16);
#pragma unroll
        for (int i = 0; i < 8; i++) w2r[g * 8 + i] = wp[i];
    }

    // finisher-role constants (threads 0..255): (bF, jlF) output element
    const int bF = tid >> 4, jlF = tid & 15;
    const int jhidF = hsid * 16 + jlF, bmF = bg * 16 + bF;
    float bhr = 0.f, bhz = 0.f, bhn = 0.f;
    const float* xgp = g_xg;
    float* yp = g_y;
    int hwF = 0, holdF = 0;
    if (tid < 256) {
        bhr = b_hh[jhidF]; bhz = b_hh[HH + jhidF]; bhn = b_hh[2 * HH + jhidF];
        xgp = g_xg + (size_t)bmF * TT * GG + jhidF;
        yp  = g_y  + (size_t)bmF * TT * HH + jhidF;
        hwF = bmF * HH + jhidF;
        holdF = (hsid * 65 + bF * 4 + (jlF >> 2)) * 4 + (jlF & 3);
    }
    float xr = 0.f, xz = 0.f, xn = 0.f;
    if (tid < 256) { xr = __ldcg(xgp); xz = __ldcg(xgp + HH); xn = __ldcg(xgp + 2 * HH); }

    const float4* hbase = hs4 + ks * 65;

    for (int t = 0; t < TT; t++) {
        const float4* src4 = (const float4*)(g_h[t & 1] + bg * 16 * HH);
#pragma unroll
        for (int q = 0; q < 4; q++) {
            int g = tid + q * 512;
            hs4[((g & 127) >> 2) * 65 + (g >> 7) * 4 + (g & 3)] = __ldcg(src4 + g);
        }
        __syncthreads();

#pragma unroll
        for (int G = 0; G < 2; G++) {
            float X0[8], X1[8], X2[8];
#pragma unroll
            for (int bb = 0; bb < 8; bb++) {
                const float4* hb = hbase + (G * 8 + bb) * 4;
                u64 a0 = 0ull, a1 = 0ull, a2 = 0ull;
#pragma unroll
                for (int q = 0; q < 4; q++) {
                    float4 v = hb[q];
                    u64 h0 = *(const u64*)&v.x, h1 = *(const u64*)&v.z;
                    ffma2(a0, h0, w2r[2 * q]);      ffma2(a0, h1, w2r[2 * q + 1]);
                    ffma2(a1, h0, w2r[8 + 2 * q]);  ffma2(a1, h1, w2r[8 + 2 * q + 1]);
                    ffma2(a2, h0, w2r[16 + 2 * q]); ffma2(a2, h1, w2r[16 + 2 * q + 1]);
                }
                float2 f0 = unpack2(a0), f1 = unpack2(a1), f2 = unpack2(a2);
                X0[bb] = f0.x + f0.y; X1[bb] = f1.x + f1.y; X2[bb] = f2.x + f2.y;
            }
            // reduce-scatter over 8 ks-lanes: X*[0] ends at batch b = G*8 + ksin
#pragma unroll
            for (int s = 4; s >= 1; s >>= 1) {
                const bool up = (ksin & s) != 0;
#pragma unroll
                for (int i = 0; i < s; i++) {
                    float v0 = up ? X0[i] : X0[i + s];
                    float v1 = up ? X1[i] : X1[i + s];
                    float v2 = up ? X2[i] : X2[i + s];
                    v0 = __shfl_xor_sync(0xffffffffu, v0, s);
                    v1 = __shfl_xor_sync(0xffffffffu, v1, s);
                    v2 = __shfl_xor_sync(0xffffffffu, v2, s);
                    X0[i] = (up ? X0[i + s] : X0[i]) + v0;
                    X1[i] = (up ? X1[i + s] : X1[i]) + v1;
                    X2[i] = (up ? X2[i + s] : X2[i]) + v2;
                }
            }
            int bown = G * 8 + ksin;
            Rsm[kshi * 817 +       bown * 17 + jl] = X0[0];
            Rsm[kshi * 817 + 272 + bown * 17 + jl] = X1[0];
            Rsm[kshi * 817 + 544 + bown * 17 + jl] = X2[0];
        }
        __syncthreads();

        if (tid < 256) {
            float sR = 0.f, sZ = 0.f, sN = 0.f;
#pragma unroll
            for (int k = 0; k < 4; k++) {
                sR += Rsm[k * 817 +       bF * 17 + jlF];
                sZ += Rsm[k * 817 + 272 + bF * 17 + jlF];
                sN += Rsm[k * 817 + 544 + bF * 17 + jlF];
            }
            float hold = ((const float*)hs4)[holdF];
            float r = 1.f / (1.f + __expf(-(xr + sR + bhr)));
            float z = 1.f / (1.f + __expf(-(xz + sZ + bhz)));
            float n = tanhf(xn + r * (sN + bhn));
            float hnew = (1.f - z) * n + z * hold;
            __stcg(&g_h[(t + 1) & 1][hwF], hnew);
            __stcg(yp, hnew);
            xgp += GG; yp += HH;
            const float* nx = (t + 1 < TT) ? xgp : g_xg;
            xr = __ldcg(nx); xz = __ldcg(nx + HH); xn = __ldcg(nx + 2 * HH);
        }
        __syncthreads();
        if (tid == 0) {
            __threadfence();
            unsigned tgt = (unsigned)(t + 1) * 32u;
            atomicAdd(&g_bar4[bg], 1u);
            while (*(volatile unsigned*)&g_bar4[bg] < tgt) __nanosleep(20);
        }
        __syncthreads();
    }
}

extern "C" void kernel_launch(void* const* d_in, const int* in_sizes, int n_in,
                              void* d_out, int out_size)
{
    const float* x    = (const float*)d_in[0];
    const float* wih0 = (const float*)d_in[1];
    const float* whh0 = (const float*)d_in[2];
    const float* bih0 = (const float*)d_in[3];
    const float* bhh0 = (const float*)d_in[4];
    const float* wih1 = (const float*)d_in[5];
    const float* whh1 = (const float*)d_in[6];
    const float* bih1 = (const float*)d_in[7];
    const float* bhh1 = (const float*)d_in[8];
    const float* fcw  = (const float*)d_in[9];
    const float* fcb  = (const float*)d_in[10];
    float* out = (float*)d_out;
    (void)in_sizes; (void)n_in; (void)out_size;

    float *xg, *y;
    cudaGetSymbolAddress((void**)&xg, g_xg);
    cudaGetSymbolAddress((void**)&y,  g_y);

    dim3 gxg(GG / 128, MM / 128);

    sgemm_bias<128,128,16,8,4><<<gxg, 256>>>(x, wih0, bih0, xg, MM, GG, II);
    k_zero<<<64, 256>>>();
    gru_scan<<<128, 512>>>(whh0, bhh0);

    sgemm_bias<128,128,16,8,4><<<gxg, 256>>>(y, wih1, bih1, xg, MM, GG, HH);
    k_zero<<<64, 256>>>();
    gru_scan<<<128, 512>>>(whh1, bhh1);

    sgemm_bias<128,64,16,8,2><<<dim3(1, MM / 128), 256>>>(y, fcw, fcb, out, MM, II, HH);
}